// round 7
// baseline (speedup 1.0000x reference)
#include <cuda_runtime.h>
#include <cuda_bf16.h>
#include <stdint.h>

#define B 128
#define C 1024
#define MARGIN 1.0f
#define THREADS 128
#define NWARP (THREADS / 32)
#define MAX_POS 256
#define VEC 8                 // C / THREADS

// Per-row (loss, denom) partials — deterministic, no float atomics.
__device__ float2 g_part[B];
// Last-block-done ticket; reset by the finishing block -> replay-safe.
__device__ unsigned int g_ticket;

__global__ void __launch_bounds__(THREADS, 1)
fused_kernel(const float* __restrict__ scores, const uint4* __restrict__ pos_mask,
             float* __restrict__ out) {
    const int row  = blockIdx.x;
    const int tid  = threadIdx.x;
    const int w    = tid >> 5;
    const int lane = tid & 31;

    __shared__ float s_pos[MAX_POS];
    __shared__ int   s_npos;
    __shared__ float s_red[NWARP];
    __shared__ int   s_last;

    if (tid == 0) s_npos = 0;

    // Mask is a 32-bit dtype (float32 or int32 — established empirically).
    // For both: positive <=> 32-bit word != 0.
    // 4 independent loads issued back-to-back: one memory-latency round (MLP=4).
    const float4 sa = ((const float4*)(scores + row * C))[tid * 2];
    const float4 sb = ((const float4*)(scores + row * C))[tid * 2 + 1];
    const uint4  ma = pos_mask[row * (C / 4) + tid * 2];
    const uint4  mb = pos_mask[row * (C / 4) + tid * 2 + 1];

    float sc[VEC] = {sa.x, sa.y, sa.z, sa.w, sb.x, sb.y, sb.z, sb.w};
    bool  m[VEC]  = {ma.x != 0u, ma.y != 0u, ma.z != 0u, ma.w != 0u,
                     mb.x != 0u, mb.y != 0u, mb.z != 0u, mb.w != 0u};

    // ---- Gather positive scores into SMEM (few positives -> cheap) ----
#pragma unroll
    for (int k = 0; k < VEC; k++) {
        if (m[k]) {
            int slot = atomicAdd(&s_npos, 1);
            if (slot < MAX_POS) s_pos[slot] = sc[k];
        }
    }
    __syncthreads();

    const int npos = min(s_npos, MAX_POS);

    // ---- Pairwise hinge: this thread's negatives vs all positives ----
    float acc = 0.0f;
#pragma unroll
    for (int k = 0; k < VEC; k++) {
        if (!m[k]) {
            const float sn = sc[k] + MARGIN;
            for (int p = 0; p < npos; p++)
                acc += fmaxf(sn - s_pos[p], 0.0f);
        }
    }

    // ---- Deterministic block reduction ----
#pragma unroll
    for (int off = 16; off > 0; off >>= 1)
        acc += __shfl_down_sync(0xFFFFFFFFu, acc, off);
    if (lane == 0) s_red[w] = acc;
    __syncthreads();

    if (tid == 0) {
        float total = 0.0f;
#pragma unroll
        for (int ww = 0; ww < NWARP; ww++) total += s_red[ww];
        float np = (float)npos;
        g_part[row] = make_float2(total, np * (float)(C - npos));
        __threadfence();  // release partial before ticket
        unsigned int ticket = atomicAdd(&g_ticket, 1u);
        s_last = (ticket == B - 1) ? 1 : 0;
    }
    __syncthreads();

    // ---- Last block: warp 0 finalizes (fixed order, bitwise deterministic) ----
    if (s_last && w == 0) {
        __threadfence();  // acquire: all blocks' partials visible
        float l = 0.0f, d = 0.0f;
#pragma unroll
        for (int j = 0; j < B / 32; j++) {
            float2 p = g_part[lane + j * 32];
            l += p.x;
            d += p.y;
        }
#pragma unroll
        for (int off = 16; off > 0; off >>= 1) {
            l += __shfl_down_sync(0xFFFFFFFFu, l, off);
            d += __shfl_down_sync(0xFFFFFFFFu, d, off);
        }
        if (lane == 0) {
            out[0] = (d == 0.0f) ? 0.0f : l / d;
            g_ticket = 0;  // reset for next graph replay
        }
    }
}

extern "C" void kernel_launch(void* const* d_in, const int* in_sizes, int n_in,
                              void* d_out, int out_size) {
    const float* scores = (const float*)d_in[0];
    const uint4* pos_mask = (const uint4*)d_in[1];
    float* out = (float*)d_out;

    fused_kernel<<<B, THREADS>>>(scores, pos_mask, out);
}